// round 7
// baseline (speedup 1.0000x reference)
#include <cuda_runtime.h>

// RegionPartitioner, input-centric ("scatter") formulation.
// out[b, r, c, i, j] = x[b, c, min(ri*32+i, 499), min(rj*32+j, 499)],
//   r = ri*15 + rj, 15x15 regions of 64x64, step 32.
// Output: (8, 225, 4, 64, 64) fp32.
//
// One thread per input float4 (b,c,row,col4): load once, store to every
// region containing it (<=2 ri x <=2 rj). Edge-replication rows/cols are
// emitted by the threads owning input row 499 / input cols 496..499.
// Reads: 32MB (1x). Writes: 118MB (exactly once per output element).

namespace {
constexpr int B  = 8;
constexpr int C  = 4;
constexpr int H  = 500;
constexpr int W  = 500;
constexpr int W4 = W / 4;       // 125 float4 per row
constexpr int RS = 64;
constexpr int NR = 15;
constexpr int R  = NR * NR;     // 225
constexpr int PER_BC = H * W4;  // 62500 threads per (b,c) image
}  // namespace

// Store val into region (ri,rj) at (i, j4); if this is the last in-bounds
// column group of an rj==14 region, also emit the replicated columns
// j4=13..15 (all = col 499 = val.w).
__device__ __forceinline__ void store_region(float4* __restrict__ out,
                                             int bc, int ri, int rj,
                                             int i, int j4, float4 val) {
    const int b = bc >> 2;
    const int c = bc & 3;
    float4* dst = out + (((long long)(b * R + ri * NR + rj) * C + c) * RS + i) * (RS / 4);
    dst[j4] = val;
    if (rj == NR - 1 && j4 == 12) {
        float4 splat = make_float4(val.w, val.w, val.w, val.w);
        dst[13] = splat;
        dst[14] = splat;
        dst[15] = splat;
    }
}

__global__ __launch_bounds__(256)
void region_partition_kernel(const float* __restrict__ x,
                             float4* __restrict__ out) {
    const int tid = blockIdx.x * blockDim.x + threadIdx.x;
    if (tid >= PER_BC) return;
    const int bc  = blockIdx.y;           // 0..31  (b*4 + c)
    const int row = tid / W4;             // 0..499
    const int c4  = tid - row * W4;       // 0..124 (float4 column group)
    const int col = c4 * 4;

    // Load this thread's input float4 exactly once.
    const float4 val = *reinterpret_cast<const float4*>(
        x + ((long long)bc * H + row) * W + col);

    // Regions containing this row: ri in [ceil((row-63)/32), floor(row/32)] ∩ [0,14]
    int riLo = (row - 63 + 31) >> 5;  if (riLo < 0)      riLo = 0;
    int riHi = row >> 5;              if (riHi > NR - 1) riHi = NR - 1;
    // Regions fully containing cols [col, col+3]:
    // rj in [ceil((col-60)/32), floor(col/32)] ∩ [0,14]
    int rjLo = (col - 60 + 31) >> 5;  if (rjLo < 0)      rjLo = 0;
    int rjHi = col >> 5;              if (rjHi > NR - 1) rjHi = NR - 1;

    for (int ri = riLo; ri <= riHi; ri++) {
        const int i = row - (ri << 5);
        for (int rj = rjLo; rj <= rjHi; rj++) {
            store_region(out, bc, ri, rj, i, c4 - (rj << 3), val);
        }
    }

    // Edge-replicated rows: region ri=14, output rows i=52..63 all read
    // input row 499. Owned by the row==499 threads.
    if (row == H - 1) {
#pragma unroll
        for (int i2 = 52; i2 < RS; i2++) {
            for (int rj = rjLo; rj <= rjHi; rj++) {
                store_region(out, bc, NR - 1, rj, i2, c4 - (rj << 3), val);
            }
        }
    }
}

extern "C" void kernel_launch(void* const* d_in, const int* in_sizes, int n_in,
                              void* d_out, int out_size) {
    const float* x = (const float*)d_in[0];
    float4* out = (float4*)d_out;

    dim3 grid((PER_BC + 255) / 256, B * C);   // (245, 32)
    region_partition_kernel<<<grid, 256>>>(x, out);
}

// round 8
// speedup vs baseline: 1.0718x; 1.0718x over previous
#include <cuda_runtime.h>

// RegionPartitioner, smem-supertile gather.
// out[b, r, c, i, j] = x[b, c, min(ri*32+i, 499), min(rj*32+j, 499)],
//   r = ri*15 + rj, 15x15 regions of 64x64, step 32.
// Output: (8, 225, 4, 64, 64) fp32.
//
// One block = one 96x96 input supertile (per b,c) covering a 2x2 group of
// overlapping regions. Tile is staged in smem once (36KB reads) instead of
// each region re-reading its 16KB from L2 (64KB) -> L2 read traffic -21%.

namespace {
constexpr int B  = 8;
constexpr int C  = 4;
constexpr int H  = 500;
constexpr int W  = 500;
constexpr int RS = 64;
constexpr int NR = 15;
constexpr int R  = NR * NR;     // 225
constexpr int TW = 96;          // supertile dim (covers 2 regions, stride 32)
constexpr int SP = 100;         // smem row pitch in floats (pad 4 -> no conflicts)
constexpr int CG = TW / 4;      // 24 float4 column-groups per tile row
constexpr int NG = 8;           // region groups per dim: 7 pairs + singleton (ri=14)
}  // namespace

__global__ __launch_bounds__(256)
void region_partition_kernel(const float* __restrict__ x,
                             float4* __restrict__ out) {
    __shared__ float s[TW * SP];          // 38400 B

    const int gxy = blockIdx.x;           // 0..63
    const int gi  = gxy >> 3;             // row-group 0..7
    const int gj  = gxy & 7;              // col-group 0..7
    const int bc  = blockIdx.y;           // 0..31
    const int b   = bc >> 2;
    const int c   = bc & 3;

    const int ri0  = gi * 2;
    const int rj0  = gj * 2;
    const int row0 = ri0 * 32;
    const int col0 = rj0 * 32;

    const float* src = x + (long long)bc * H * W;
    const int t = threadIdx.x;

    // ---- Load 96x96 tile into smem (2304 float4, 9 per thread). ----
#pragma unroll
    for (int k = 0; k < 9; k++) {
        const int l = t + k * 256;        // 0..2303, exact
        const int rr = l / CG;
        const int q  = l - rr * CG;
        int row = row0 + rr; if (row > H - 1) row = H - 1;   // gi==7 only
        const int col = col0 + q * 4;
        const float* p = src + row * W;
        float4 v;
        if (col + 3 <= W - 1) {
            v = *reinterpret_cast<const float4*>(p + col);
        } else {                                              // gj==7 only
            v.x = p[min(col,     W - 1)];
            v.y = p[min(col + 1, W - 1)];
            v.z = p[min(col + 2, W - 1)];
            v.w = p[min(col + 3, W - 1)];
        }
        *reinterpret_cast<float4*>(s + rr * SP + q * 4) = v;
    }
    __syncthreads();

    // ---- Emit up to 2x2 regions from smem. ----
    const int j4 = t & 15;                // float4 column in region row
    const int i0 = t >> 4;                // 0..15
    const int nri = (ri0 + 1 <= NR - 1) ? 2 : 1;
    const int nrj = (rj0 + 1 <= NR - 1) ? 2 : 1;

    for (int di = 0; di < nri; di++) {
        for (int dj = 0; dj < nrj; dj++) {
            const int rgn = b * R + (ri0 + di) * NR + (rj0 + dj);
            float4* dst = out + ((long long)rgn * C + c) * (RS * RS / 4);
            const float* sbase = s + di * 32 * SP + dj * 32 + j4 * 4;
#pragma unroll
            for (int k = 0; k < 4; k++) {
                const int i = i0 + k * 16;
                const float4 v =
                    *reinterpret_cast<const float4*>(sbase + i * SP);
                dst[i * 16 + j4] = v;
            }
        }
    }
}

extern "C" void kernel_launch(void* const* d_in, const int* in_sizes, int n_in,
                              void* d_out, int out_size) {
    const float* x = (const float*)d_in[0];
    float4* out = (float4*)d_out;

    dim3 grid(NG * NG, B * C);   // (64, 32) = 2048 blocks
    region_partition_kernel<<<grid, 256>>>(x, out);
}

// round 9
// speedup vs baseline: 1.2793x; 1.1935x over previous
#include <cuda_runtime.h>

// RegionPartitioner, band-aligned one-load/four-store formulation.
// out[b, r, c, i, j] = x[b, c, min(ri*32+i, 499), min(rj*32+j, 499)],
//   r = ri*15 + rj, 15x15 regions of 64x64, step 32.
// Output: (8, 225, 4, 64, 64) fp32.
//
// Key structure: output i<32 of region ri comes uniquely from input row-band
// rb=ri; i>=32 uniquely from band rb=ri+1 (same for columns). So one thread
// per input float4 in a 32x32 band loads ONCE and stores to its <=2x2 region
// positions; every output element is written exactly once. Edge replication
// (rows/cols 500..511 -> 499) is handled by load-time clamping in band 15.
// L2 traffic: 33MB reads + 118MB writes (vs 118+118 for the pure gather).

namespace {
constexpr int B  = 8;
constexpr int C  = 4;
constexpr int H  = 500;
constexpr int W  = 500;
constexpr int RS = 64;
constexpr int NR = 15;
constexpr int R  = NR * NR;     // 225
constexpr int NB = 16;          // 32-wide bands per dim (band 15 = clamped edge)
}  // namespace

__global__ __launch_bounds__(256)
void region_partition_kernel(const float* __restrict__ x,
                             float4* __restrict__ out) {
    const int blk = blockIdx.x;          // 0..255
    const int rb  = blk >> 4;            // row band 0..15
    const int cb  = blk & 15;            // col band 0..15
    const int bc  = blockIdx.y;          // 0..31
    const int b   = bc >> 2;
    const int c   = bc & 3;

    const int t  = threadIdx.x;          // 0..255
    const int tc = t & 7;                // float4 group within band (8 x 16B = 32 cols)
    const int tr = t >> 3;               // row within band 0..31

    // ---- Load this thread's input float4 exactly once (clamped). ----
    const int row  = min(rb * 32 + tr, H - 1);
    const int col0 = cb * 32 + tc * 4;
    const float* src = x + ((long long)bc * H + row) * W;
    float4 v;
    if (col0 + 3 <= W - 1) {
        v = *reinterpret_cast<const float4*>(src + col0);
    } else {                             // cb==15, tc>=5 only: cols >= 500
        v.x = src[min(col0,     W - 1)];
        v.y = src[min(col0 + 1, W - 1)];
        v.z = src[min(col0 + 2, W - 1)];
        v.w = src[min(col0 + 3, W - 1)];
    }

    // ---- Target regions (block-uniform branches; no divergence). ----
    int ris[2], is_[2], nri = 0;
    if (rb >= 1)      { ris[nri] = rb - 1; is_[nri] = 32 + tr; nri++; }
    if (rb <= NR - 1) { ris[nri] = rb;     is_[nri] = tr;      nri++; }
    int rjs[2], js[2], nrj = 0;
    if (cb >= 1)      { rjs[nrj] = cb - 1; js[nrj] = 8 + tc;   nrj++; }
    if (cb <= NR - 1) { rjs[nrj] = cb;     js[nrj] = tc;       nrj++; }

    // Stores: for fixed (ri,rj,i), 8 consecutive tc write a contiguous 128B run.
    const long long outbase = (long long)b * R;
#pragma unroll
    for (int a = 0; a < 2; a++) {
        if (a >= nri) break;
        const int rowoff = is_[a] * (RS / 4);
#pragma unroll
        for (int d = 0; d < 2; d++) {
            if (d >= nrj) break;
            const long long rgn = outbase + ris[a] * NR + rjs[d];
            out[((rgn * C + c) * RS) * (RS / 4) + rowoff + js[d]] = v;
        }
    }
}

extern "C" void kernel_launch(void* const* d_in, const int* in_sizes, int n_in,
                              void* d_out, int out_size) {
    const float* x = (const float*)d_in[0];
    float4* out = (float4*)d_out;

    dim3 grid(NB * NB, B * C);   // (256, 32) = 8192 blocks
    region_partition_kernel<<<grid, 256>>>(x, out);
}